// round 1
// baseline (speedup 1.0000x reference)
#include <cuda_runtime.h>
#include <math_constants.h>

// Problem constants
#define B_  8
#define S_  1024
#define H_  12
#define D_  64
#define E_  768
#define ST  68        // padded smem row stride (floats): keeps float4 alignment,
                      // makes 8-lane LDS.128 phases contiguous-128B -> conflict free

// Scratch for projected Q/K/V, layout [b*H+h][s][d]
__device__ float g_q[B_*H_*S_*D_];
__device__ float g_k[B_*H_*S_*D_];
__device__ float g_v[B_*H_*S_*D_];

// ---------------------------------------------------------------------------
// Projection kernel: per (b, h, 64-row chunk), compute q/k/v = x @ W[h] + b[h]
// X transposed in smem (Xt[d][row]); W natural (Ws[d][e]); outer-product over d.
// ---------------------------------------------------------------------------
__global__ __launch_bounds__(256, 2)
void proj_kernel(const float* __restrict__ seq,
                 const float* __restrict__ Wq, const float* __restrict__ bq,
                 const float* __restrict__ Wk, const float* __restrict__ bk,
                 const float* __restrict__ Wv, const float* __restrict__ bv)
{
    __shared__ float Xt[64 * ST];   // Xt[d][row]
    __shared__ float Ws[64 * ST];   // Ws[d][e]

    const int tid = threadIdx.x;
    const int tx  = tid & 15;       // output-dim group
    const int ty  = tid >> 4;       // row group
    const int sc  = blockIdx.x;     // 0..15
    const int h   = blockIdx.y;     // 0..11
    const int b   = blockIdx.z;     // 0..7
    const int s0  = sc * 64;

    // Load X slab [64 rows x 64 dims] for this head, transposed into smem.
    const float* xbase = seq + ((size_t)b * S_ + s0) * E_ + h * D_;
#pragma unroll
    for (int i = 0; i < 16; i++) {
        int idx = i * 256 + tid;
        int r = idx >> 6, d = idx & 63;
        Xt[d * ST + r] = xbase[(size_t)r * E_ + d];   // coalesced gmem read
    }

    const float* Wm[3] = { Wq + h * D_ * D_, Wk + h * D_ * D_, Wv + h * D_ * D_ };
    const float* bm[3] = { bq + h * D_,      bk + h * D_,      bv + h * D_      };
    const size_t obase = ((size_t)(b * H_ + h) * S_ + s0) * D_;
    float* om[3] = { g_q + obase, g_k + obase, g_v + obase };

    for (int mtx = 0; mtx < 3; mtx++) {
        __syncthreads();                       // also covers Xt load on first pass
#pragma unroll
        for (int i = 0; i < 16; i++) {
            int idx = i * 256 + tid;           // W[h] is [d][e] row-major
            Ws[(idx >> 6) * ST + (idx & 63)] = Wm[mtx][idx];
        }
        __syncthreads();

        float acc[4][4];
#pragma unroll
        for (int i = 0; i < 4; i++)
#pragma unroll
            for (int j = 0; j < 4; j++) acc[i][j] = 0.f;

#pragma unroll 16
        for (int d = 0; d < 64; d++) {
            float4 xf = *(const float4*)(Xt + d * ST + ty * 4);  // broadcast
            float4 wf = *(const float4*)(Ws + d * ST + tx * 4);  // conflict-free
            float xv[4] = { xf.x, xf.y, xf.z, xf.w };
            float wv[4] = { wf.x, wf.y, wf.z, wf.w };
#pragma unroll
            for (int i = 0; i < 4; i++)
#pragma unroll
                for (int j = 0; j < 4; j++)
                    acc[i][j] = fmaf(xv[i], wv[j], acc[i][j]);
        }

        float4 bb = *(const float4*)(bm[mtx] + tx * 4);
        float bvv[4] = { bb.x, bb.y, bb.z, bb.w };
        float* outp = om[mtx];
#pragma unroll
        for (int i = 0; i < 4; i++) {
            float4 o;
            o.x = acc[i][0] + bvv[0];
            o.y = acc[i][1] + bvv[1];
            o.z = acc[i][2] + bvv[2];
            o.w = acc[i][3] + bvv[3];
            *(float4*)(outp + (size_t)(ty * 4 + i) * D_ + tx * 4) = o;
        }
    }
}

// ---------------------------------------------------------------------------
// Attention kernel: flash-style online softmax.
// CTA = (b, h, 64 q-rows). Loop over 16 key tiles of 64.
// Logits GEMM: Qt[d][row] x Kt[d][key] outer-product over d.
// PV GEMM:     Ps[key][row] x Vs[key][dim] outer-product over key.
// Thread (ty,tx) owns rows ty*4..+3 and cols tx*4..+3 of each 64x64 tile.
// ---------------------------------------------------------------------------
__global__ __launch_bounds__(256, 2)
void attn_kernel(float* __restrict__ out)
{
    extern __shared__ float sm[];
    float* Qt = sm;                 // [64 d][ST rows]
    float* Kt = sm + 64 * ST;       // [64 d][ST keys]
    float* Vs = sm + 2 * 64 * ST;   // [64 key][ST dims]
    float* Ps = sm + 3 * 64 * ST;   // [64 key][ST rows]

    const int tid = threadIdx.x;
    const int tx  = tid & 15;
    const int ty  = tid >> 4;
    const int qc  = blockIdx.x;
    const int h   = blockIdx.y;
    const int b   = blockIdx.z;
    const int bh  = b * H_ + h;
    const int q0  = qc * 64;

    const float* Qg = g_q + (size_t)bh * S_ * D_;
    const float* Kg = g_k + (size_t)bh * S_ * D_;
    const float* Vg = g_v + (size_t)bh * S_ * D_;

    // Load Q tile transposed (once per CTA)
#pragma unroll
    for (int i = 0; i < 16; i++) {
        int idx = i * 256 + tid;
        int r = idx >> 6, d = idx & 63;
        Qt[d * ST + r] = Qg[(size_t)(q0 + r) * D_ + d];
    }

    float mrow[4], lrow[4], acc[4][4];
#pragma unroll
    for (int i = 0; i < 4; i++) {
        mrow[i] = -CUDART_INF_F;
        lrow[i] = 0.f;
#pragma unroll
        for (int j = 0; j < 4; j++) acc[i][j] = 0.f;
    }

    for (int kt = 0; kt < 16; kt++) {
        __syncthreads();   // prior iteration's reads of Kt/Vs/Ps are done
        const float* kp = Kg + (size_t)kt * 64 * D_;
        const float* vp = Vg + (size_t)kt * 64 * D_;
#pragma unroll
        for (int i = 0; i < 16; i++) {
            int idx = i * 256 + tid;
            int j = idx >> 6, d = idx & 63;
            Kt[d * ST + j] = kp[idx];   // transposed write (8-way, amortized)
            Vs[j * ST + d] = vp[idx];   // natural write, conflict-free
        }
        __syncthreads();

        // ---- logits tile: s[i][j] = q_row(i) . k_key(j) ----
        float s[4][4];
#pragma unroll
        for (int i = 0; i < 4; i++)
#pragma unroll
            for (int j = 0; j < 4; j++) s[i][j] = 0.f;

#pragma unroll 16
        for (int d = 0; d < 64; d++) {
            float4 qf = *(const float4*)(Qt + d * ST + ty * 4);  // broadcast
            float4 kf = *(const float4*)(Kt + d * ST + tx * 4);  // conflict-free
            float qv[4] = { qf.x, qf.y, qf.z, qf.w };
            float kv[4] = { kf.x, kf.y, kf.z, kf.w };
#pragma unroll
            for (int i = 0; i < 4; i++)
#pragma unroll
                for (int j = 0; j < 4; j++)
                    s[i][j] = fmaf(qv[i], kv[j], s[i][j]);
        }

        // ---- online softmax update (row stats across the 16-lane tx group) ----
        float p[4][4];
#pragma unroll
        for (int i = 0; i < 4; i++) {
            float tm = fmaxf(fmaxf(s[i][0], s[i][1]), fmaxf(s[i][2], s[i][3]));
            tm = fmaxf(tm, __shfl_xor_sync(0xffffffffu, tm, 1));
            tm = fmaxf(tm, __shfl_xor_sync(0xffffffffu, tm, 2));
            tm = fmaxf(tm, __shfl_xor_sync(0xffffffffu, tm, 4));
            tm = fmaxf(tm, __shfl_xor_sync(0xffffffffu, tm, 8));
            float mn = fmaxf(mrow[i], tm);
            float scale = __expf(mrow[i] - mn);   // exp(-inf)=0 on first tile
            mrow[i] = mn;
            float rs = 0.f;
#pragma unroll
            for (int j = 0; j < 4; j++) {
                p[i][j] = __expf(s[i][j] - mn);
                rs += p[i][j];
            }
            rs += __shfl_xor_sync(0xffffffffu, rs, 1);
            rs += __shfl_xor_sync(0xffffffffu, rs, 2);
            rs += __shfl_xor_sync(0xffffffffu, rs, 4);
            rs += __shfl_xor_sync(0xffffffffu, rs, 8);
            lrow[i] = lrow[i] * scale + rs;
#pragma unroll
            for (int j = 0; j < 4; j++) acc[i][j] *= scale;
        }

        // ---- stage P transposed: Ps[key][row] ----
#pragma unroll
        for (int j = 0; j < 4; j++) {
            float4 pv = make_float4(p[0][j], p[1][j], p[2][j], p[3][j]);
            *(float4*)(Ps + (tx * 4 + j) * ST + ty * 4) = pv;
        }
        __syncthreads();

        // ---- O += P @ V : outer-product over keys ----
#pragma unroll 16
        for (int j = 0; j < 64; j++) {
            float4 pf = *(const float4*)(Ps + j * ST + ty * 4);  // broadcast
            float4 vf = *(const float4*)(Vs + j * ST + tx * 4);  // conflict-free
            float pv[4] = { pf.x, pf.y, pf.z, pf.w };
            float vv[4] = { vf.x, vf.y, vf.z, vf.w };
#pragma unroll
            for (int i = 0; i < 4; i++)
#pragma unroll
                for (int c = 0; c < 4; c++)
                    acc[i][c] = fmaf(pv[i], vv[c], acc[i][c]);
        }
    }

    // ---- epilogue: normalize and write out[b][s][h*64+e] ----
    float* ob = out + ((size_t)b * S_ + q0) * E_ + h * D_;
#pragma unroll
    for (int i = 0; i < 4; i++) {
        float inv = 1.f / lrow[i];
        float4 o = make_float4(acc[i][0] * inv, acc[i][1] * inv,
                               acc[i][2] * inv, acc[i][3] * inv);
        *(float4*)(ob + (size_t)(ty * 4 + i) * E_ + tx * 4) = o;
    }
}

// ---------------------------------------------------------------------------
extern "C" void kernel_launch(void* const* d_in, const int* in_sizes, int n_in,
                              void* d_out, int out_size)
{
    const float* seq = (const float*)d_in[0];
    const float* Wq  = (const float*)d_in[1];
    const float* bq  = (const float*)d_in[2];
    const float* Wk  = (const float*)d_in[3];
    const float* bk  = (const float*)d_in[4];
    const float* Wv  = (const float*)d_in[5];
    const float* bv  = (const float*)d_in[6];
    float* out = (float*)d_out;

    dim3 grid(S_ / 64, H_, B_);   // 16 x 12 x 8 = 1536 CTAs

    proj_kernel<<<grid, 256>>>(seq, Wq, bq, Wk, bk, Wv, bv);

    const int attn_smem = 4 * 64 * ST * (int)sizeof(float);  // 69632 B
    cudaFuncSetAttribute(attn_kernel,
                         cudaFuncAttributeMaxDynamicSharedMemorySize, attn_smem);
    attn_kernel<<<grid, 256, attn_smem>>>(out);
}

// round 2
// speedup vs baseline: 1.5911x; 1.5911x over previous
#include <cuda_runtime.h>
#include <math_constants.h>

#define B_  8
#define S_  1024
#define H_  12
#define D_  64
#define E_  768
#define QST 132     // stride for 128-row transposed tiles (float4-aligned)
#define KST 68      // stride for 64-wide tiles

// Scratch for projected Q/K/V, layout [b*H+h][s][d]
__device__ float g_q[B_*H_*S_*D_];
__device__ float g_k[B_*H_*S_*D_];
__device__ float g_v[B_*H_*S_*D_];

// ---------------------------------------------------------------------------
// Projection: per (b, h, 128-row chunk), q/k/v = x @ W[h] + b[h].
// 8x4 register tile per thread, 256 threads -> 128 rows x 64 outs.
// ---------------------------------------------------------------------------
__global__ __launch_bounds__(256, 1)
void proj_kernel(const float* __restrict__ seq,
                 const float* __restrict__ Wq, const float* __restrict__ bq,
                 const float* __restrict__ Wk, const float* __restrict__ bk,
                 const float* __restrict__ Wv, const float* __restrict__ bv)
{
    extern __shared__ float sm[];
    float* Xt = sm;               // [64 d][QST rows]
    float* Ws = sm + 64 * QST;    // [64 d][KST outs]

    const int tid = threadIdx.x;
    const int tx  = tid & 15;     // out-dim group (4 each)
    const int ty  = tid >> 4;     // row group (8 each)
    const int sc  = blockIdx.x;   // 0..7
    const int h   = blockIdx.y;
    const int b   = blockIdx.z;
    const int s0  = sc * 128;

    // X slab [128 rows x 64 d], transposed into smem
    const float* xbase = seq + ((size_t)b * S_ + s0) * E_ + h * D_;
#pragma unroll
    for (int i = 0; i < 32; i++) {
        int idx = i * 256 + tid;
        int r = idx >> 6, d = idx & 63;
        Xt[d * QST + r] = xbase[(size_t)r * E_ + d];
    }

    const float* Wm[3] = { Wq + h * D_ * D_, Wk + h * D_ * D_, Wv + h * D_ * D_ };
    const float* bm[3] = { bq + h * D_,      bk + h * D_,      bv + h * D_      };
    const size_t obase = ((size_t)(b * H_ + h) * S_ + s0) * D_;
    float* om[3] = { g_q + obase, g_k + obase, g_v + obase };

    for (int mtx = 0; mtx < 3; mtx++) {
        __syncthreads();
#pragma unroll
        for (int i = 0; i < 16; i++) {
            int idx = i * 256 + tid;
            Ws[(idx >> 6) * KST + (idx & 63)] = Wm[mtx][idx];
        }
        __syncthreads();

        float acc[8][4];
#pragma unroll
        for (int i = 0; i < 8; i++)
#pragma unroll
            for (int j = 0; j < 4; j++) acc[i][j] = 0.f;

#pragma unroll 8
        for (int d = 0; d < 64; d++) {
            float4 x0 = *(const float4*)(Xt + d * QST + ty * 8);
            float4 x1 = *(const float4*)(Xt + d * QST + ty * 8 + 4);
            float4 wf = *(const float4*)(Ws + d * KST + tx * 4);
            float xv[8] = { x0.x, x0.y, x0.z, x0.w, x1.x, x1.y, x1.z, x1.w };
            float wv[4] = { wf.x, wf.y, wf.z, wf.w };
#pragma unroll
            for (int i = 0; i < 8; i++)
#pragma unroll
                for (int j = 0; j < 4; j++)
                    acc[i][j] = fmaf(xv[i], wv[j], acc[i][j]);
        }

        float4 bb = *(const float4*)(bm[mtx] + tx * 4);
        float bvv[4] = { bb.x, bb.y, bb.z, bb.w };
        float* outp = om[mtx];
#pragma unroll
        for (int i = 0; i < 8; i++) {
            float4 o;
            o.x = acc[i][0] + bvv[0];
            o.y = acc[i][1] + bvv[1];
            o.z = acc[i][2] + bvv[2];
            o.w = acc[i][3] + bvv[3];
            *(float4*)(outp + (size_t)(ty * 8 + i) * D_ + tx * 4) = o;
        }
    }
}

// ---------------------------------------------------------------------------
// Attention: flash-style online softmax, 128 q-rows per CTA, 16 key tiles of 64.
// 8x4 register tile per thread for both GEMMs.
// ---------------------------------------------------------------------------
__global__ __launch_bounds__(256, 1)
void attn_kernel(float* __restrict__ out)
{
    extern __shared__ float sm[];
    float* Qt = sm;                         // [64 d][QST rows]    33792B
    float* Kt = sm + 64 * QST;              // [64 d][KST keys]    17408B
    float* Vs = sm + 64 * QST + 64 * KST;   // [64 key][KST dims]  17408B
    float* Ps = sm + 64 * QST + 2*64*KST;   // [64 key][QST rows]  33792B

    const int tid = threadIdx.x;
    const int tx  = tid & 15;     // key group (4 each)
    const int ty  = tid >> 4;     // row group (8 each)
    const int qc  = blockIdx.x;   // 0..7
    const int h   = blockIdx.y;
    const int b   = blockIdx.z;
    const int bh  = b * H_ + h;
    const int q0  = qc * 128;

    const float* Qg = g_q + (size_t)bh * S_ * D_;
    const float* Kg = g_k + (size_t)bh * S_ * D_;
    const float* Vg = g_v + (size_t)bh * S_ * D_;

    // Q tile transposed (once per CTA): 128 rows x 64 d
#pragma unroll
    for (int i = 0; i < 32; i++) {
        int idx = i * 256 + tid;
        int r = idx >> 6, d = idx & 63;
        Qt[d * QST + r] = Qg[(size_t)(q0 + r) * D_ + d];
    }

    float mrow[8], lrow[8], acc[8][4];
#pragma unroll
    for (int i = 0; i < 8; i++) {
        mrow[i] = -CUDART_INF_F;
        lrow[i] = 0.f;
#pragma unroll
        for (int j = 0; j < 4; j++) acc[i][j] = 0.f;
    }

    for (int kt = 0; kt < 16; kt++) {
        __syncthreads();   // previous tile's Kt/Vs/Ps reads are done
        const float* kp = Kg + (size_t)kt * 64 * D_;
        const float* vp = Vg + (size_t)kt * 64 * D_;
#pragma unroll
        for (int i = 0; i < 16; i++) {
            int idx = i * 256 + tid;
            int j = idx >> 6, d = idx & 63;
            Kt[d * KST + j] = kp[idx];   // transposed (4-way conflict, amortized)
            Vs[j * KST + d] = vp[idx];   // natural
        }
        __syncthreads();

        // ---- logits tile: s[i][j] = q_row . k_key ----
        float s[8][4];
#pragma unroll
        for (int i = 0; i < 8; i++)
#pragma unroll
            for (int j = 0; j < 4; j++) s[i][j] = 0.f;

#pragma unroll 8
        for (int d = 0; d < 64; d++) {
            float4 q0f = *(const float4*)(Qt + d * QST + ty * 8);
            float4 q1f = *(const float4*)(Qt + d * QST + ty * 8 + 4);
            float4 kf  = *(const float4*)(Kt + d * KST + tx * 4);
            float qv[8] = { q0f.x, q0f.y, q0f.z, q0f.w, q1f.x, q1f.y, q1f.z, q1f.w };
            float kv[4] = { kf.x, kf.y, kf.z, kf.w };
#pragma unroll
            for (int i = 0; i < 8; i++)
#pragma unroll
                for (int j = 0; j < 4; j++)
                    s[i][j] = fmaf(qv[i], kv[j], s[i][j]);
        }

        // ---- online softmax (row stats across 16-lane tx groups) ----
#pragma unroll
        for (int i = 0; i < 8; i++) {
            float tm = fmaxf(fmaxf(s[i][0], s[i][1]), fmaxf(s[i][2], s[i][3]));
            tm = fmaxf(tm, __shfl_xor_sync(0xffffffffu, tm, 1));
            tm = fmaxf(tm, __shfl_xor_sync(0xffffffffu, tm, 2));
            tm = fmaxf(tm, __shfl_xor_sync(0xffffffffu, tm, 4));
            tm = fmaxf(tm, __shfl_xor_sync(0xffffffffu, tm, 8));
            float mn = fmaxf(mrow[i], tm);
            float scale = __expf(mrow[i] - mn);   // exp(-inf)=0 first tile
            mrow[i] = mn;
            float rs = 0.f;
#pragma unroll
            for (int j = 0; j < 4; j++) {
                s[i][j] = __expf(s[i][j] - mn);   // p overwrites s
                rs += s[i][j];
            }
            rs += __shfl_xor_sync(0xffffffffu, rs, 1);
            rs += __shfl_xor_sync(0xffffffffu, rs, 2);
            rs += __shfl_xor_sync(0xffffffffu, rs, 4);
            rs += __shfl_xor_sync(0xffffffffu, rs, 8);
            lrow[i] = lrow[i] * scale + rs;
#pragma unroll
            for (int j = 0; j < 4; j++) acc[i][j] *= scale;
        }

        // ---- stage P transposed: Ps[key][row] ----
#pragma unroll
        for (int j = 0; j < 4; j++) {
            int key = tx * 4 + j;
            *(float4*)(Ps + key * QST + ty * 8) =
                make_float4(s[0][j], s[1][j], s[2][j], s[3][j]);
            *(float4*)(Ps + key * QST + ty * 8 + 4) =
                make_float4(s[4][j], s[5][j], s[6][j], s[7][j]);
        }
        __syncthreads();

        // ---- O += P @ V ----
#pragma unroll 8
        for (int j = 0; j < 64; j++) {
            float4 p0f = *(const float4*)(Ps + j * QST + ty * 8);
            float4 p1f = *(const float4*)(Ps + j * QST + ty * 8 + 4);
            float4 vf  = *(const float4*)(Vs + j * KST + tx * 4);
            float pv[8] = { p0f.x, p0f.y, p0f.z, p0f.w, p1f.x, p1f.y, p1f.z, p1f.w };
            float vv[4] = { vf.x, vf.y, vf.z, vf.w };
#pragma unroll
            for (int i = 0; i < 8; i++)
#pragma unroll
                for (int c = 0; c < 4; c++)
                    acc[i][c] = fmaf(pv[i], vv[c], acc[i][c]);
        }
    }

    // ---- epilogue ----
    float* ob = out + ((size_t)b * S_ + q0) * E_ + h * D_;
#pragma unroll
    for (int i = 0; i < 8; i++) {
        float inv = 1.f / lrow[i];
        *(float4*)(ob + (size_t)(ty * 8 + i) * E_ + tx * 4) =
            make_float4(acc[i][0] * inv, acc[i][1] * inv,
                        acc[i][2] * inv, acc[i][3] * inv);
    }
}

// ---------------------------------------------------------------------------
extern "C" void kernel_launch(void* const* d_in, const int* in_sizes, int n_in,
                              void* d_out, int out_size)
{
    const float* seq = (const float*)d_in[0];
    const float* Wq  = (const float*)d_in[1];
    const float* bq  = (const float*)d_in[2];
    const float* Wk  = (const float*)d_in[3];
    const float* bk  = (const float*)d_in[4];
    const float* Wv  = (const float*)d_in[5];
    const float* bv  = (const float*)d_in[6];
    float* out = (float*)d_out;

    dim3 grid(S_ / 128, H_, B_);   // 8 x 12 x 8 = 768 CTAs

    const int proj_smem = (64 * QST + 64 * KST) * (int)sizeof(float);          // 51200
    const int attn_smem = (64 * QST * 2 + 2 * 64 * KST) * (int)sizeof(float);  // 102400

    static bool attr_set = false;
    if (!attr_set) {
        cudaFuncSetAttribute(proj_kernel,
                             cudaFuncAttributeMaxDynamicSharedMemorySize, proj_smem);
        cudaFuncSetAttribute(attn_kernel,
                             cudaFuncAttributeMaxDynamicSharedMemorySize, attn_smem);
        attr_set = true;
    }

    proj_kernel<<<grid, 256, proj_smem>>>(seq, Wq, bq, Wk, bk, Wv, bv);
    attn_kernel<<<grid, 256, attn_smem>>>(out);
}

// round 3
// speedup vs baseline: 1.8880x; 1.1866x over previous
#include <cuda_runtime.h>
#include <math_constants.h>

#define B_  8
#define S_  1024
#define H_  12
#define D_  64
#define E_  768
#define QST 132     // stride for 128-row transposed tiles (float4/double2-aligned)
#define KST 68      // stride for 64-wide tiles

// Scratch for projected Q/K/V, layout [b*H+h][s][d]
__device__ float g_q[B_*H_*S_*D_];
__device__ float g_k[B_*H_*S_*D_];
__device__ float g_v[B_*H_*S_*D_];

// ---- packed f32x2 helpers (sm_100+ PTX) ------------------------------------
__device__ __forceinline__ double ffma2(double a, double b, double c) {
    double d;
    asm("fma.rn.f32x2 %0, %1, %2, %3;" : "=d"(d) : "d"(a), "d"(b), "d"(c));
    return d;
}
__device__ __forceinline__ double fmul2(double a, double b) {
    double d;
    asm("mul.rn.f32x2 %0, %1, %2;" : "=d"(d) : "d"(a), "d"(b));
    return d;
}
__device__ __forceinline__ double fpack2(float lo, float hi) {
    double d;
    asm("mov.b64 %0, {%1, %2};" : "=d"(d) : "f"(lo), "f"(hi));
    return d;
}
__device__ __forceinline__ double fdup2(float v) {
    double d;
    asm("mov.b64 %0, {%1, %1};" : "=d"(d) : "f"(v));
    return d;
}
__device__ __forceinline__ void funpack2(double d, float& lo, float& hi) {
    asm("mov.b64 {%0, %1}, %2;" : "=f"(lo), "=f"(hi) : "d"(d));
}

// ---------------------------------------------------------------------------
// Projection: per (b, h, 128-row chunk), q/k/v = x @ W[h] + b[h].
// 8x4 per thread, accumulators packed over row pairs (f32x2).
// ---------------------------------------------------------------------------
__global__ __launch_bounds__(256, 1)
void proj_kernel(const float* __restrict__ seq,
                 const float* __restrict__ Wq, const float* __restrict__ bq,
                 const float* __restrict__ Wk, const float* __restrict__ bk,
                 const float* __restrict__ Wv, const float* __restrict__ bv)
{
    extern __shared__ float sm[];
    float* Xt = sm;               // [64 d][QST rows]
    float* Ws = sm + 64 * QST;    // [64 d][KST outs]

    const int tid = threadIdx.x;
    const int tx  = tid & 15;
    const int ty  = tid >> 4;
    const int s0  = blockIdx.x * 128;
    const int h   = blockIdx.y;
    const int b   = blockIdx.z;

    const float* xbase = seq + ((size_t)b * S_ + s0) * E_ + h * D_;
#pragma unroll
    for (int i = 0; i < 32; i++) {
        int idx = i * 256 + tid;
        int r = idx >> 6, d = idx & 63;
        Xt[d * QST + r] = xbase[(size_t)r * E_ + d];
    }

    const float* Wm[3] = { Wq + h * D_ * D_, Wk + h * D_ * D_, Wv + h * D_ * D_ };
    const float* bm[3] = { bq + h * D_,      bk + h * D_,      bv + h * D_      };
    const size_t obase = ((size_t)(b * H_ + h) * S_ + s0) * D_;
    float* om[3] = { g_q + obase, g_k + obase, g_v + obase };

    for (int mtx = 0; mtx < 3; mtx++) {
        __syncthreads();
#pragma unroll
        for (int i = 0; i < 16; i++) {
            int idx = i * 256 + tid;
            Ws[(idx >> 6) * KST + (idx & 63)] = Wm[mtx][idx];
        }
        __syncthreads();

        double accp[4][4];   // (row-pair, col)
#pragma unroll
        for (int rp = 0; rp < 4; rp++)
#pragma unroll
            for (int c = 0; c < 4; c++) accp[rp][c] = 0.0;

#pragma unroll 8
        for (int d = 0; d < 64; d++) {
            double2 qa = *(const double2*)(Xt + d * QST + ty * 8);
            double2 qb = *(const double2*)(Xt + d * QST + ty * 8 + 4);
            float4 wf  = *(const float4*)(Ws + d * KST + tx * 4);
            double qp[4] = { qa.x, qa.y, qb.x, qb.y };
            double wd[4] = { fdup2(wf.x), fdup2(wf.y), fdup2(wf.z), fdup2(wf.w) };
#pragma unroll
            for (int rp = 0; rp < 4; rp++)
#pragma unroll
                for (int c = 0; c < 4; c++)
                    accp[rp][c] = ffma2(qp[rp], wd[c], accp[rp][c]);
        }

        float4 bb = *(const float4*)(bm[mtx] + tx * 4);
        float bvv[4] = { bb.x, bb.y, bb.z, bb.w };
        float* outp = om[mtx];
#pragma unroll
        for (int rp = 0; rp < 4; rp++) {
            float lo[4], hi[4];
#pragma unroll
            for (int c = 0; c < 4; c++) funpack2(accp[rp][c], lo[c], hi[c]);
            *(float4*)(outp + (size_t)(ty * 8 + rp * 2) * D_ + tx * 4) =
                make_float4(lo[0] + bvv[0], lo[1] + bvv[1], lo[2] + bvv[2], lo[3] + bvv[3]);
            *(float4*)(outp + (size_t)(ty * 8 + rp * 2 + 1) * D_ + tx * 4) =
                make_float4(hi[0] + bvv[0], hi[1] + bvv[1], hi[2] + bvv[2], hi[3] + bvv[3]);
        }
    }
}

// ---------------------------------------------------------------------------
// Attention: flash-style, 128 q-rows/CTA, 16 key tiles of 64, f32x2 FMAs.
// Thread (ty,tx): rows ty*8..+7 (as 4 row-pairs), cols tx*4..+3.
// ---------------------------------------------------------------------------
__global__ __launch_bounds__(256, 1)
void attn_kernel(float* __restrict__ out)
{
    extern __shared__ float sm[];
    float* Qt = sm;                         // [64 d][QST rows]
    float* Kt = sm + 64 * QST;              // [64 d][KST keys]
    float* Vs = sm + 64 * QST + 64 * KST;   // [64 key][KST dims]
    float* Ps = sm + 64 * QST + 2*64*KST;   // [64 key][QST rows]

    const int tid = threadIdx.x;
    const int tx  = tid & 15;
    const int ty  = tid >> 4;
    const int q0  = blockIdx.x * 128;
    const int h   = blockIdx.y;
    const int b   = blockIdx.z;
    const int bh  = b * H_ + h;

    const float* Qg = g_q + (size_t)bh * S_ * D_;
    const float* Kg = g_k + (size_t)bh * S_ * D_;
    const float* Vg = g_v + (size_t)bh * S_ * D_;

    // Q tile transposed (once)
#pragma unroll
    for (int i = 0; i < 32; i++) {
        int idx = i * 256 + tid;
        int r = idx >> 6, d = idx & 63;
        Qt[d * QST + r] = Qg[(size_t)(q0 + r) * D_ + d];
    }

    float mrow[8], lrow[8];
    double accp[4][4];   // O accumulator: (row-pair, col)
#pragma unroll
    for (int i = 0; i < 8; i++) { mrow[i] = -CUDART_INF_F; lrow[i] = 0.f; }
#pragma unroll
    for (int rp = 0; rp < 4; rp++)
#pragma unroll
        for (int c = 0; c < 4; c++) accp[rp][c] = 0.0;

    // Prefetch tile 0 K/V into registers (float4 x4 each)
    float4 kreg[4], vreg[4];
    {
        const float4* kp = (const float4*)Kg;
        const float4* vp = (const float4*)Vg;
#pragma unroll
        for (int i = 0; i < 4; i++) {
            kreg[i] = kp[i * 256 + tid];
            vreg[i] = vp[i * 256 + tid];
        }
    }

    for (int kt = 0; kt < 16; kt++) {
        __syncthreads();   // previous tile's Kt/Vs/Ps reads done
        // store prefetched tile: K transposed, V natural
#pragma unroll
        for (int i = 0; i < 4; i++) {
            int idx4 = i * 256 + tid;         // float4 index within 64x64 tile
            int j = idx4 >> 4;                // row (key)
            int dbase = (idx4 & 15) * 4;      // dim base
            Kt[(dbase + 0) * KST + j] = kreg[i].x;
            Kt[(dbase + 1) * KST + j] = kreg[i].y;
            Kt[(dbase + 2) * KST + j] = kreg[i].z;
            Kt[(dbase + 3) * KST + j] = kreg[i].w;
            *(float4*)(Vs + j * KST + dbase) = vreg[i];
        }
        __syncthreads();

        // prefetch next tile while computing
        if (kt < 15) {
            const float4* kp = (const float4*)(Kg + (size_t)(kt + 1) * 64 * D_);
            const float4* vp = (const float4*)(Vg + (size_t)(kt + 1) * 64 * D_);
#pragma unroll
            for (int i = 0; i < 4; i++) {
                kreg[i] = kp[i * 256 + tid];
                vreg[i] = vp[i * 256 + tid];
            }
        }

        // ---- logits: sp[rp][c] = packed (row2rp, row2rp+1) dot k_col ----
        double sp[4][4];
#pragma unroll
        for (int rp = 0; rp < 4; rp++)
#pragma unroll
            for (int c = 0; c < 4; c++) sp[rp][c] = 0.0;

#pragma unroll 8
        for (int d = 0; d < 64; d++) {
            double2 qa = *(const double2*)(Qt + d * QST + ty * 8);
            double2 qb = *(const double2*)(Qt + d * QST + ty * 8 + 4);
            float4 kf  = *(const float4*)(Kt + d * KST + tx * 4);
            double qp[4] = { qa.x, qa.y, qb.x, qb.y };
            double kd[4] = { fdup2(kf.x), fdup2(kf.y), fdup2(kf.z), fdup2(kf.w) };
#pragma unroll
            for (int rp = 0; rp < 4; rp++)
#pragma unroll
                for (int c = 0; c < 4; c++)
                    sp[rp][c] = ffma2(qp[rp], kd[c], sp[rp][c]);
        }

        // unpack logits
        float s[8][4];
#pragma unroll
        for (int rp = 0; rp < 4; rp++)
#pragma unroll
            for (int c = 0; c < 4; c++)
                funpack2(sp[rp][c], s[2 * rp][c], s[2 * rp + 1][c]);

        // ---- online softmax (row stats across 16-lane tx groups) ----
        float scale[8];
#pragma unroll
        for (int i = 0; i < 8; i++) {
            float tm = fmaxf(fmaxf(s[i][0], s[i][1]), fmaxf(s[i][2], s[i][3]));
            tm = fmaxf(tm, __shfl_xor_sync(0xffffffffu, tm, 1));
            tm = fmaxf(tm, __shfl_xor_sync(0xffffffffu, tm, 2));
            tm = fmaxf(tm, __shfl_xor_sync(0xffffffffu, tm, 4));
            tm = fmaxf(tm, __shfl_xor_sync(0xffffffffu, tm, 8));
            float mn = fmaxf(mrow[i], tm);
            scale[i] = __expf(mrow[i] - mn);   // exp(-inf)=0 first tile
            mrow[i] = mn;
            float rs = 0.f;
#pragma unroll
            for (int j = 0; j < 4; j++) {
                s[i][j] = __expf(s[i][j] - mn);
                rs += s[i][j];
            }
            rs += __shfl_xor_sync(0xffffffffu, rs, 1);
            rs += __shfl_xor_sync(0xffffffffu, rs, 2);
            rs += __shfl_xor_sync(0xffffffffu, rs, 4);
            rs += __shfl_xor_sync(0xffffffffu, rs, 8);
            lrow[i] = lrow[i] * scale[i] + rs;
        }
        // rescale O accumulators (packed over row pairs)
#pragma unroll
        for (int rp = 0; rp < 4; rp++) {
            double sc2 = fpack2(scale[2 * rp], scale[2 * rp + 1]);
#pragma unroll
            for (int c = 0; c < 4; c++) accp[rp][c] = fmul2(accp[rp][c], sc2);
        }

        // ---- stage P transposed: Ps[key][row] ----
#pragma unroll
        for (int j = 0; j < 4; j++) {
            int key = tx * 4 + j;
            *(float4*)(Ps + key * QST + ty * 8) =
                make_float4(s[0][j], s[1][j], s[2][j], s[3][j]);
            *(float4*)(Ps + key * QST + ty * 8 + 4) =
                make_float4(s[4][j], s[5][j], s[6][j], s[7][j]);
        }
        __syncthreads();

        // ---- O += P @ V (packed over row pairs) ----
#pragma unroll 8
        for (int j = 0; j < 64; j++) {
            double2 pa = *(const double2*)(Ps + j * QST + ty * 8);
            double2 pb = *(const double2*)(Ps + j * QST + ty * 8 + 4);
            float4 vf  = *(const float4*)(Vs + j * KST + tx * 4);
            double pp[4] = { pa.x, pa.y, pb.x, pb.y };
            double vd[4] = { fdup2(vf.x), fdup2(vf.y), fdup2(vf.z), fdup2(vf.w) };
#pragma unroll
            for (int rp = 0; rp < 4; rp++)
#pragma unroll
                for (int c = 0; c < 4; c++)
                    accp[rp][c] = ffma2(pp[rp], vd[c], accp[rp][c]);
        }
    }

    // ---- epilogue ----
    float* ob = out + ((size_t)b * S_ + q0) * E_ + h * D_;
#pragma unroll
    for (int rp = 0; rp < 4; rp++) {
        float lo[4], hi[4];
#pragma unroll
        for (int c = 0; c < 4; c++) funpack2(accp[rp][c], lo[c], hi[c]);
        float inv0 = 1.f / lrow[2 * rp];
        float inv1 = 1.f / lrow[2 * rp + 1];
        *(float4*)(ob + (size_t)(ty * 8 + rp * 2) * E_ + tx * 4) =
            make_float4(lo[0] * inv0, lo[1] * inv0, lo[2] * inv0, lo[3] * inv0);
        *(float4*)(ob + (size_t)(ty * 8 + rp * 2 + 1) * E_ + tx * 4) =
            make_float4(hi[0] * inv1, hi[1] * inv1, hi[2] * inv1, hi[3] * inv1);
    }
}

// ---------------------------------------------------------------------------
extern "C" void kernel_launch(void* const* d_in, const int* in_sizes, int n_in,
                              void* d_out, int out_size)
{
    const float* seq = (const float*)d_in[0];
    const float* Wq  = (const float*)d_in[1];
    const float* bq  = (const float*)d_in[2];
    const float* Wk  = (const float*)d_in[3];
    const float* bk  = (const float*)d_in[4];
    const float* Wv  = (const float*)d_in[5];
    const float* bv  = (const float*)d_in[6];
    float* out = (float*)d_out;

    dim3 grid(S_ / 128, H_, B_);   // 8 x 12 x 8 = 768 CTAs

    const int proj_smem = (64 * QST + 64 * KST) * (int)sizeof(float);          // 51200
    const int attn_smem = (64 * QST * 2 + 2 * 64 * KST) * (int)sizeof(float);  // 102400

    cudaFuncSetAttribute(proj_kernel,
                         cudaFuncAttributeMaxDynamicSharedMemorySize, proj_smem);
    cudaFuncSetAttribute(attn_kernel,
                         cudaFuncAttributeMaxDynamicSharedMemorySize, attn_smem);

    proj_kernel<<<grid, 256, proj_smem>>>(seq, Wq, bq, Wk, bk, Wv, bv);
    attn_kernel<<<grid, 256, attn_smem>>>(out);
}